// round 7
// baseline (speedup 1.0000x reference)
#include <cuda_runtime.h>

// CRF loss, T=512, B=1024, K=48. One warp per batch element (grid 1024, one
// wave). Lanes 0..23 own output-state pair (2l, 2l+1); lanes 24..31 run the
// same code on clamped/dummy data (no divergence in the mainloop -> no
// BSSY/BSYNC). Linear-space recursion, exact power-of-2 renorm every 2 steps.
// smem P stored {P_2i, P_2i+1}; one broadcast LDS.128 feeds 4 input states;
// 48 fma.rn.f32x2 across 8 accumulators. Loop unrolled x2 over ping-pong.

#define TT 512
#define BB 1024
#define KK 48
#define START_TAG 46
#define STOP_TAG  47
#define LN2F 0.6931471805599453f
#define PFD 6                      // prefetch depth

__device__ float g_partial[BB];
__device__ int   g_count = 0;      // last block resets to 0 (graph-replay safe)

__device__ __forceinline__ unsigned long long pack2(float lo, float hi) {
    unsigned long long r;
    asm("mov.b64 %0, {%1, %2};" : "=l"(r) : "f"(lo), "f"(hi));
    return r;
}
__device__ __forceinline__ void unpack2(unsigned long long v, float& lo, float& hi) {
    asm("mov.b64 {%0, %1}, %2;" : "=f"(lo), "=f"(hi) : "l"(v));
}
__device__ __forceinline__ unsigned long long fma2(unsigned long long a,
                                                   unsigned long long b,
                                                   unsigned long long c) {
    unsigned long long d;
    asm("fma.rn.f32x2 %0, %1, %2, %3;" : "=l"(d) : "l"(a), "l"(b), "l"(c));
    return d;
}
__device__ __forceinline__ unsigned long long add2(unsigned long long a,
                                                   unsigned long long b) {
    unsigned long long d;
    asm("add.rn.f32x2 %0, %1, %2;" : "=l"(d) : "l"(a), "l"(b));
    return d;
}

// One recursion step: read PIN (24 real pairs), write POUT[lane].
// RENORM: extract power-of-2 scale from P[0]'s exponent (exact).
#define STEP(PIN, POUT, FC, RENORM)                                          \
    do {                                                                     \
        float ef0 = __expf((FC).x);                                          \
        float ef1 = __expf((FC).y);                                          \
        const ulonglong2* pv = (const ulonglong2*)(PIN);                     \
        ulonglong2 e0 = pv[0];                                               \
        unsigned long long c0 = fma2(e0.x, etp0[0], 0ull);                   \
        unsigned long long c2 = fma2(e0.y, etp0[1], 0ull);                   \
        unsigned long long c4 = fma2(e0.x, etp1[0], 0ull);                   \
        unsigned long long c6 = fma2(e0.y, etp1[1], 0ull);                   \
        unsigned long long c1 = 0ull, c3 = 0ull, c5 = 0ull, c7 = 0ull;       \
        _Pragma("unroll")                                                    \
        for (int q = 1; q < 12; q++) {                                       \
            ulonglong2 e = pv[q];                                            \
            if (q & 1) {                                                     \
                c1 = fma2(e.x, etp0[2*q],     c1);                           \
                c3 = fma2(e.y, etp0[2*q + 1], c3);                           \
                c5 = fma2(e.x, etp1[2*q],     c5);                           \
                c7 = fma2(e.y, etp1[2*q + 1], c7);                           \
            } else {                                                         \
                c0 = fma2(e.x, etp0[2*q],     c0);                           \
                c2 = fma2(e.y, etp0[2*q + 1], c2);                           \
                c4 = fma2(e.x, etp1[2*q],     c4);                           \
                c6 = fma2(e.y, etp1[2*q + 1], c6);                           \
            }                                                                \
        }                                                                    \
        unsigned long long sum0 = add2(add2(c0, c1), add2(c2, c3));          \
        unsigned long long sum1 = add2(add2(c4, c5), add2(c6, c7));          \
        float k = 1.0f;                                                      \
        if (RENORM) {                                                        \
            unsigned int pexp = ((unsigned)e0.x) >> 23;                      \
            int pe = (pexp - 1u < 254u) ? (int)pexp - 127 : 0;               \
            Cint += pe;                                                      \
            k = __uint_as_float((unsigned)(127 - pe) << 23);                 \
        }                                                                    \
        float m0 = ef0 * k, m1 = ef1 * k;                                    \
        float l0, h0, l1, h1;                                                \
        unpack2(sum0, l0, h0);                                               \
        unpack2(sum1, l1, h1);                                               \
        (POUT)[lane] = make_float2((l0 + h0) * m0, (l1 + h1) * m1);          \
    } while (0)

__global__ void __launch_bounds__(32, 1) crf_kernel(
    const float* __restrict__ feats,
    const float* __restrict__ trans,
    const int*   __restrict__ tags,
    const int*   __restrict__ lengths,
    float*       __restrict__ out)
{
    __shared__ __align__(16) float2 s_p[2][32];    // pairs; 24..31 are pads
    __shared__ float s_trans[KK * KK];

    const int b    = blockIdx.x;
    const int lane = threadIdx.x;
    const bool act = (lane < 24);
    const int sc = act ? 2 * lane : 44;            // clamped state index
    const int s0 = sc, s1 = sc + 1;
    const int len = __ldg(lengths + b);

    for (int i = lane; i < KK * KK; i += 32) s_trans[i] = trans[i];
    {
        float2 z = make_float2(0.0f, 0.0f);
        s_p[0][lane] = (lane == 23) ? make_float2(1.0f, 0.0f) : z;  // START=46
        s_p[1][lane] = z;
    }
    __syncwarp();

    // etp0[i] = {exp(T[s0,2i]), exp(T[s0,2i+1])}, etp1 likewise for s1
    unsigned long long etp0[24], etp1[24];
    #pragma unroll
    for (int i = 0; i < 24; i++) {
        etp0[i] = pack2(__expf(s_trans[s0 * KK + 2*i]),
                        __expf(s_trans[s0 * KK + 2*i + 1]));
        etp1[i] = pack2(__expf(s_trans[s1 * KK + 2*i]),
                        __expf(s_trans[s1 * KK + 2*i + 1]));   // exp(-1e4)=0
    }

    const float* fb = feats + b * KK;
    const size_t FS = (size_t)BB * KK;             // floats per time step

    // raw-feat prefetch pipeline, depth 6; running pointer
    float2 r1 = {0,0}, r2 = {0,0}, r3 = {0,0}, r4 = {0,0}, r5 = {0,0}, r6 = {0,0};
    r1 = __ldg((const float2*)(fb + sc));
    if (1 < len) r2 = __ldg((const float2*)(fb + 1 * FS + sc));
    if (2 < len) r3 = __ldg((const float2*)(fb + 2 * FS + sc));
    if (3 < len) r4 = __ldg((const float2*)(fb + 3 * FS + sc));
    if (4 < len) r5 = __ldg((const float2*)(fb + 4 * FS + sc));
    if (5 < len) r6 = __ldg((const float2*)(fb + 5 * FS + sc));
    const float2* pf = (const float2*)(fb + sc) + (size_t)PFD * (FS / 2);
    const int pre = len - PFD;                     // loads valid while t < pre

    int Cint = 0;
    __syncwarp();

    int t = 0;
    #pragma unroll 1
    while (t + 1 < len) {
        // step A: s_p[0] -> s_p[1], with renorm
        {
            float2 fc = r1;
            r1 = r2; r2 = r3; r3 = r4; r4 = r5; r5 = r6;
            r6 = (t < pre) ? __ldg(pf) : make_float2(0.0f, 0.0f);
            pf += FS / 2;
            STEP(s_p[0], s_p[1], fc, true);
        }
        __syncwarp();
        // step B: s_p[1] -> s_p[0], no renorm (range-safe, see analysis)
        {
            float2 fc = r1;
            r1 = r2; r2 = r3; r3 = r4; r4 = r5; r5 = r6;
            r6 = (t + 1 < pre) ? __ldg(pf) : make_float2(0.0f, 0.0f);
            pf += FS / 2;
            STEP(s_p[1], s_p[0], fc, false);
        }
        __syncwarp();
        t += 2;
    }
    if (t < len) {                                 // odd tail step
        float2 fc = r1;
        STEP(s_p[0], s_p[1], fc, true);
        __syncwarp();
    }

    // final P lives in s_p[len & 1]
    float v = 0.0f;
    if (act) {
        float2 P = s_p[len & 1][lane];
        v = P.x * __expf(s_trans[STOP_TAG * KK + s0])
          + P.y * __expf(s_trans[STOP_TAG * KK + s1]);
    }
    #pragma unroll
    for (int o = 16; o; o >>= 1) v += __shfl_xor_sync(~0u, v, o);
    float logz = (float)Cint * LN2F + __logf(v);   // lane 0's Cint valid

    // gold score: strided over t, warp reduce
    const int* tg = tags + b * TT;
    float g = 0.0f;
    for (int q = lane; q < len; q += 32) {
        int nxt = __ldg(tg + q);
        int prv = (q == 0) ? START_TAG : __ldg(tg + q - 1);
        g += s_trans[nxt * KK + prv] + __ldg(fb + (size_t)q * FS + nxt);
    }
    #pragma unroll
    for (int o = 16; o; o >>= 1) g += __shfl_xor_sync(~0u, g, o);

    int last = 0;
    if (lane == 0) {
        float gold = g + s_trans[STOP_TAG * KK + __ldg(tg + len - 1)];
        g_partial[b] = logz - gold;
        __threadfence();
        int prev = atomicAdd(&g_count, 1);
        last = (prev == BB - 1);
    }
    last = __shfl_sync(~0u, last, 0);

    // last block: deterministic fixed-order final reduction, reset counter
    if (last) {
        __threadfence();
        float a = 0.0f;
        #pragma unroll
        for (int i = 0; i < BB / 32; i++)
            a += g_partial[lane + i * 32];
        #pragma unroll
        for (int o = 16; o; o >>= 1) a += __shfl_xor_sync(~0u, a, o);
        if (lane == 0) {
            out[0] = a;
            g_count = 0;                           // replay-safe reset
        }
    }
}

extern "C" void kernel_launch(void* const* d_in, const int* in_sizes, int n_in,
                              void* d_out, int out_size) {
    const float* feats   = (const float*)d_in[0];
    const float* trans   = (const float*)d_in[1];
    const int*   tags    = (const int*)d_in[2];
    const int*   lengths = (const int*)d_in[3];
    crf_kernel<<<BB, 32>>>(feats, trans, tags, lengths, (float*)d_out);
}

// round 8
// speedup vs baseline: 1.0539x; 1.0539x over previous
#include <cuda_runtime.h>

// CRF loss, T=512, B=1024, K=48. One warp per batch element (grid 1024, one
// wave). R8: a pre-pass computes a length-balancing permutation so each SM
// group (bid % 148) receives an equal mix of sequence lengths, ordered so the
// arrival-pairing of warps onto SMSPs pairs longest-with-shortest. The main
// recursion is R7's: linear-space, exact power-of-2 renorm (folded into ex2),
// natural float2 packing, 48 fma.rn.f32x2 / 8 accumulators, branchless lanes.

#define TT 512
#define BB 1024
#define KK 48
#define START_TAG 46
#define STOP_TAG  47
#define LN2F  0.6931471805599453f
#define LOG2E 1.4426950408889634f
#define PFD 6                      // prefetch depth
#define NSM 148

__device__ float g_partial[BB];
__device__ int   g_perm[BB];
__device__ int   g_count = 0;      // last block resets to 0 (graph-replay safe)

__device__ __forceinline__ unsigned long long pack2(float lo, float hi) {
    unsigned long long r;
    asm("mov.b64 %0, {%1, %2};" : "=l"(r) : "f"(lo), "f"(hi));
    return r;
}
__device__ __forceinline__ void unpack2(unsigned long long v, float& lo, float& hi) {
    asm("mov.b64 {%0, %1}, %2;" : "=f"(lo), "=f"(hi) : "l"(v));
}
__device__ __forceinline__ unsigned long long fma2(unsigned long long a,
                                                   unsigned long long b,
                                                   unsigned long long c) {
    unsigned long long d;
    asm("fma.rn.f32x2 %0, %1, %2, %3;" : "=l"(d) : "l"(a), "l"(b), "l"(c));
    return d;
}
__device__ __forceinline__ unsigned long long add2(unsigned long long a,
                                                   unsigned long long b) {
    unsigned long long d;
    asm("add.rn.f32x2 %0, %1, %2;" : "=l"(d) : "l"(a), "l"(b));
    return d;
}
__device__ __forceinline__ float ex2f(float x) {
    float r;
    asm("ex2.approx.f32 %0, %1;" : "=f"(r) : "f"(x));
    return r;
}

// ---------- pre-pass: length-balancing permutation -------------------------
// rank k (0 = longest) -> round r = k/148, q = k%148; serpentine group
// g = r odd ? 147-q : q. Groups g<136 have 7 slots (bids g+148s, s=0..6),
// g>=136 have 6. Within-group slot order pairs long with short under the
// arrival model (s0,s4),(s1,s5),(s2,s6), s3 solo:
//   7 slots: m0->s3, m1->s0, m2->s1, m3->s2, m4->s6, m5->s5, m6->s4
//   6 slots: m0->s3, m1->s2, m2->s0, m3->s1, m4->s5, m5->s4
__global__ void perm_kernel(const int* __restrict__ lengths) {
    __shared__ int s_len[BB];
    const int tid = threadIdx.x;
    const int b = blockIdx.x * 512 + tid;
    s_len[tid] = lengths[tid];
    s_len[tid + 512] = lengths[tid + 512];
    __syncthreads();

    const int lb = s_len[b];
    int k = 0;
    #pragma unroll 8
    for (int j = 0; j < BB; j++) {
        int lj = s_len[j];
        k += (lj > lb) || (lj == lb && j < b);
    }
    const int r = k / NSM;
    const int q = k - r * NSM;
    const int g = (r & 1) ? (NSM - 1 - q) : q;      // r=6 -> q<136, in range
    const unsigned map = (g < 136) ? 0x4562103u : 0x0451023u;
    const int s = (map >> (4 * r)) & 15;
    g_perm[g + NSM * s] = b;
}

// ---------- main recursion (R7 body + perm + ex2-folded renorm) ------------
#define STEP(PIN, POUT, FC, RENORM)                                          \
    do {                                                                     \
        const ulonglong2* pv = (const ulonglong2*)(PIN);                     \
        ulonglong2 e0 = pv[0];                                               \
        unsigned long long c0 = fma2(e0.x, etp0[0], 0ull);                   \
        unsigned long long c2 = fma2(e0.y, etp0[1], 0ull);                   \
        unsigned long long c4 = fma2(e0.x, etp1[0], 0ull);                   \
        unsigned long long c6 = fma2(e0.y, etp1[1], 0ull);                   \
        unsigned long long c1 = 0ull, c3 = 0ull, c5 = 0ull, c7 = 0ull;       \
        _Pragma("unroll")                                                    \
        for (int q = 1; q < 12; q++) {                                       \
            ulonglong2 e = pv[q];                                            \
            if (q & 1) {                                                     \
                c1 = fma2(e.x, etp0[2*q],     c1);                           \
                c3 = fma2(e.y, etp0[2*q + 1], c3);                           \
                c5 = fma2(e.x, etp1[2*q],     c5);                           \
                c7 = fma2(e.y, etp1[2*q + 1], c7);                           \
            } else {                                                         \
                c0 = fma2(e.x, etp0[2*q],     c0);                           \
                c2 = fma2(e.y, etp0[2*q + 1], c2);                           \
                c4 = fma2(e.x, etp1[2*q],     c4);                           \
                c6 = fma2(e.y, etp1[2*q + 1], c6);                           \
            }                                                                \
        }                                                                    \
        unsigned long long sum0 = add2(add2(c0, c1), add2(c2, c3));          \
        unsigned long long sum1 = add2(add2(c4, c5), add2(c6, c7));          \
        float fpe = 0.0f;                                                    \
        if (RENORM) {                                                        \
            unsigned int pexp = ((unsigned)e0.x) >> 23;                      \
            int pe = (pexp - 1u < 254u) ? (int)pexp - 127 : 0;               \
            Cint += pe;                                                      \
            fpe = (float)(-pe);                                              \
        }                                                                    \
        float m0 = ex2f(fmaf((FC).x, LOG2E, fpe));                           \
        float m1 = ex2f(fmaf((FC).y, LOG2E, fpe));                           \
        float l0, h0, l1, h1;                                                \
        unpack2(sum0, l0, h0);                                               \
        unpack2(sum1, l1, h1);                                               \
        (POUT)[lane] = make_float2((l0 + h0) * m0, (l1 + h1) * m1);          \
    } while (0)

__global__ void __launch_bounds__(32, 1) crf_kernel(
    const float* __restrict__ feats,
    const float* __restrict__ trans,
    const int*   __restrict__ tags,
    const int*   __restrict__ lengths,
    float*       __restrict__ out)
{
    __shared__ __align__(16) float2 s_p[2][32];    // pairs; 24..31 are pads
    __shared__ float s_trans[KK * KK];

    const int b    = __ldg(&g_perm[blockIdx.x]);
    const int lane = threadIdx.x;
    const bool act = (lane < 24);
    const int sc = act ? 2 * lane : 44;            // clamped state index
    const int s0 = sc, s1 = sc + 1;
    const int len = __ldg(lengths + b);

    for (int i = lane; i < KK * KK; i += 32) s_trans[i] = trans[i];
    {
        float2 z = make_float2(0.0f, 0.0f);
        s_p[0][lane] = (lane == 23) ? make_float2(1.0f, 0.0f) : z;  // START=46
        s_p[1][lane] = z;
    }
    __syncwarp();

    // etp0[i] = {exp(T[s0,2i]), exp(T[s0,2i+1])}, etp1 likewise for s1
    unsigned long long etp0[24], etp1[24];
    #pragma unroll
    for (int i = 0; i < 24; i++) {
        etp0[i] = pack2(__expf(s_trans[s0 * KK + 2*i]),
                        __expf(s_trans[s0 * KK + 2*i + 1]));
        etp1[i] = pack2(__expf(s_trans[s1 * KK + 2*i]),
                        __expf(s_trans[s1 * KK + 2*i + 1]));   // exp(-1e4)=0
    }

    const float* fb = feats + b * KK;
    const size_t FS = (size_t)BB * KK;             // floats per time step

    // raw-feat prefetch pipeline, depth 6; running pointer
    float2 r1 = {0,0}, r2 = {0,0}, r3 = {0,0}, r4 = {0,0}, r5 = {0,0}, r6 = {0,0};
    r1 = __ldg((const float2*)(fb + sc));
    if (1 < len) r2 = __ldg((const float2*)(fb + 1 * FS + sc));
    if (2 < len) r3 = __ldg((const float2*)(fb + 2 * FS + sc));
    if (3 < len) r4 = __ldg((const float2*)(fb + 3 * FS + sc));
    if (4 < len) r5 = __ldg((const float2*)(fb + 4 * FS + sc));
    if (5 < len) r6 = __ldg((const float2*)(fb + 5 * FS + sc));
    const float2* pf = (const float2*)(fb + sc) + (size_t)PFD * (FS / 2);
    const int pre = len - PFD;                     // loads valid while t < pre

    int Cint = 0;
    __syncwarp();

    int t = 0;
    #pragma unroll 1
    while (t + 1 < len) {
        // step A: s_p[0] -> s_p[1], with renorm
        {
            float2 fc = r1;
            r1 = r2; r2 = r3; r3 = r4; r4 = r5; r5 = r6;
            r6 = (t < pre) ? __ldg(pf) : make_float2(0.0f, 0.0f);
            pf += FS / 2;
            STEP(s_p[0], s_p[1], fc, true);
        }
        __syncwarp();
        // step B: s_p[1] -> s_p[0], no renorm (range-safe)
        {
            float2 fc = r1;
            r1 = r2; r2 = r3; r3 = r4; r4 = r5; r5 = r6;
            r6 = (t + 1 < pre) ? __ldg(pf) : make_float2(0.0f, 0.0f);
            pf += FS / 2;
            STEP(s_p[1], s_p[0], fc, false);
        }
        __syncwarp();
        t += 2;
    }
    if (t < len) {                                 // odd tail step
        float2 fc = r1;
        STEP(s_p[0], s_p[1], fc, true);
        __syncwarp();
    }

    // final P lives in s_p[len & 1]
    float v = 0.0f;
    if (act) {
        float2 P = s_p[len & 1][lane];
        v = P.x * __expf(s_trans[STOP_TAG * KK + s0])
          + P.y * __expf(s_trans[STOP_TAG * KK + s1]);
    }
    #pragma unroll
    for (int o = 16; o; o >>= 1) v += __shfl_xor_sync(~0u, v, o);
    float logz = (float)Cint * LN2F + __logf(v);   // lane 0's Cint valid

    // gold score: strided over t, warp reduce
    const int* tg = tags + b * TT;
    float g = 0.0f;
    for (int q = lane; q < len; q += 32) {
        int nxt = __ldg(tg + q);
        int prv = (q == 0) ? START_TAG : __ldg(tg + q - 1);
        g += s_trans[nxt * KK + prv] + __ldg(fb + (size_t)q * FS + nxt);
    }
    #pragma unroll
    for (int o = 16; o; o >>= 1) g += __shfl_xor_sync(~0u, g, o);

    int last = 0;
    if (lane == 0) {
        float gold = g + s_trans[STOP_TAG * KK + __ldg(tg + len - 1)];
        g_partial[b] = logz - gold;
        __threadfence();
        int prev = atomicAdd(&g_count, 1);
        last = (prev == BB - 1);
    }
    last = __shfl_sync(~0u, last, 0);

    // last block: deterministic fixed-order final reduction, reset counter
    if (last) {
        __threadfence();
        float a = 0.0f;
        #pragma unroll
        for (int i = 0; i < BB / 32; i++)
            a += g_partial[lane + i * 32];
        #pragma unroll
        for (int o = 16; o; o >>= 1) a += __shfl_xor_sync(~0u, a, o);
        if (lane == 0) {
            out[0] = a;
            g_count = 0;                           // replay-safe reset
        }
    }
}

extern "C" void kernel_launch(void* const* d_in, const int* in_sizes, int n_in,
                              void* d_out, int out_size) {
    const float* feats   = (const float*)d_in[0];
    const float* trans   = (const float*)d_in[1];
    const int*   tags    = (const int*)d_in[2];
    const int*   lengths = (const int*)d_in[3];
    perm_kernel<<<2, 512>>>(lengths);
    crf_kernel<<<BB, 32>>>(feats, trans, tags, lengths, (float*)d_out);
}